// round 14
// baseline (speedup 1.0000x reference)
#include <cuda_runtime.h>
#include <cuda_fp16.h>
#include <math.h>
#include <stdint.h>

// Problem constants
#define BB   2
#define TT   512
#define DM   1024
#define DH   4096
#define DD   4
#define VV   32000
#define ROWS (BB*TT*DD)   // 4096
#define BTN  (BB*TT)      // 1024
#define SPLITK 4

// Scratch (static device globals — no allocation allowed)
__device__ __half  g_Shi[ROWS*DM];
__device__ __half  g_Slo[ROWS*DM];
__device__ __half2 g_W1h[(DM/2)*DH];
__device__ __half2 g_W1l[(DM/2)*DH];
__device__ __half2 g_W2h[(DH/2)*DM];
__device__ float   g_G  [ROWS*DH];         // fp32-exact gelu (beta path)
__device__ __half  g_Gh [ROWS*DH];         // fp16 gelu (q path)
__device__ float   g_S2f[ROWS*DM];         // fp32 S2 accumulator (bias-inited, atomics)
__device__ __half  g_S2h[ROWS*DM];
__device__ __half2 g_Wqh[(DM/2)*VV];
__device__ float   g_w2b[DH+1];
__device__ float   g_beta[ROWS];
__device__ float   g_sum[ROWS];            // per-row sum(exp(q)); |q| small, no max needed
__device__ int     g_idx [BTN];
__device__ int     g_cnt [1];
__device__ double  g_acc[4];

// ============================================================================
__device__ __forceinline__ uint32_t smem_u32(const void* p) {
    uint32_t a;
    asm("{ .reg .u64 t; cvta.to.shared.u64 t, %1; cvt.u32.u64 %0, t; }"
        : "=r"(a) : "l"(p));
    return a;
}
__device__ __forceinline__ void cp16(uint32_t s, const void* g) {
    asm volatile("cp.async.cg.shared.global [%0], [%1], 16;" :: "r"(s), "l"(g));
}
#define CP_COMMIT() asm volatile("cp.async.commit_group;" ::: "memory")
#define CP_WAIT0()  asm volatile("cp.async.wait_group 0;" ::: "memory")

__device__ __forceinline__ void mma_f16_16x8x16(float* d, const uint32_t* a,
                                                const uint32_t* b) {
    asm volatile(
        "mma.sync.aligned.m16n8k16.row.col.f32.f16.f16.f32 "
        "{%0,%1,%2,%3}, {%4,%5,%6,%7}, {%8,%9}, {%0,%1,%2,%3};"
        : "+f"(d[0]), "+f"(d[1]), "+f"(d[2]), "+f"(d[3])
        : "r"(a[0]), "r"(a[1]), "r"(a[2]), "r"(a[3]), "r"(b[0]), "r"(b[1]));
}

// ============================================================================
// compact + zero g_acc + zero g_sum
__global__ void compact_kernel(const int* __restrict__ mask) {
    __shared__ int pre[BTN];
    int tid = threadIdx.x;
    if (tid < 4) g_acc[tid] = 0.0;
#pragma unroll
    for (int j = 0; j < 4; j++) g_sum[j * BTN + tid] = 0.f;
    int m = (mask[tid] != 0) ? 1 : 0;
    pre[tid] = m;
    __syncthreads();
    for (int o = 1; o < BTN; o <<= 1) {
        int v = (tid >= o) ? pre[tid - o] : 0;
        __syncthreads();
        pre[tid] += v;
        __syncthreads();
    }
    int mv = pre[BTN - 1];
    if (m) g_idx[pre[tid] - 1] = tid;
    if (tid >= mv) g_idx[tid] = 0;
    if (tid == 0) g_cnt[0] = mv * 4;
}

// ---------------------------------------------------------------------------
__global__ void zero_fill_kernel(const int* __restrict__ mask,
                                 float* __restrict__ q,
                                 float* __restrict__ obeta,
                                 float* __restrict__ ok)
{
    int bt = blockIdx.x;
    if (mask[bt] != 0) return;
    int tid = threadIdx.x;
    float4* dst = (float4*)(q + (size_t)bt * 4 * VV);
#pragma unroll 4
    for (int i = tid; i < 32000; i += 256) dst[i] = make_float4(0.f, 0.f, 0.f, 0.f);
    if (tid < 4) {
        obeta[bt * 4 + tid] = 0.f;
        ok[bt * 4 + tid]    = 0.f;
    }
}

// ---------------------------------------------------------------------------
__global__ void w2b_kernel(const float* __restrict__ W2, const float* __restrict__ Wb,
                           const float* __restrict__ b2, const float* __restrict__ bb)
{
    if (blockIdx.x == DH / 8) {
        __shared__ float red[256];
        int tid = threadIdx.x;
        float s = 0.f;
        for (int i = tid; i < DM; i += 256) s += b2[i] * Wb[i];
        red[tid] = s; __syncthreads();
        for (int o = 128; o > 0; o >>= 1) { if (tid < o) red[tid] += red[tid + o]; __syncthreads(); }
        if (tid == 0) g_w2b[DH] = red[0] + bb[0];
        return;
    }
    int w = threadIdx.x >> 5, lane = threadIdx.x & 31;
    int j = blockIdx.x * 8 + w;
    const float* row = W2 + (size_t)j * DM;
    float s = 0.f;
    for (int i = lane; i < DM; i += 32) s += row[i] * Wb[i];
#pragma unroll
    for (int o = 16; o > 0; o >>= 1) s += __shfl_xor_sync(0xffffffffu, s, o);
    if (lane == 0) g_w2b[j] = s;
}

// ---------------------------------------------------------------------------
// Init S2f rows with bias b2 (atomic accumulation target for mlp2)
__global__ void s2init_kernel(const float* __restrict__ b2)
{
    int i4 = blockIdx.x * 256 + threadIdx.x;     // over ROWS*DM/4
    int c  = (i4 & 255) * 4;
    *(float4*)&g_S2f[(size_t)i4 * 4] = *(const float4*)&b2[c];
}

// ---------------------------------------------------------------------------
__global__ void packw_kernel(const float* __restrict__ W,
                             __half2* __restrict__ Dh, __half2* __restrict__ Dl,
                             int N)
{
    int n  = blockIdx.x * 256 + threadIdx.x;
    int k2 = blockIdx.y;
    float x0 = W[(size_t)(2 * k2    ) * N + n];
    float x1 = W[(size_t)(2 * k2 + 1) * N + n];
    __half h0 = __float2half_rn(x0), h1 = __float2half_rn(x1);
    Dh[(size_t)k2 * N + n] = __halves2half2(h0, h1);
    if (Dl)
        Dl[(size_t)k2 * N + n] = __halves2half2(
            __float2half_rn(x0 - __half2float(h0)),
            __float2half_rn(x1 - __half2float(h1)));
}

// ---------------------------------------------------------------------------
__global__ void s_kernel(const float* __restrict__ H, const int* __restrict__ ids,
                         const float* __restrict__ emb, const float* __restrict__ demb,
                         const float* __restrict__ lng, const float* __restrict__ lnb)
{
    int rp = blockIdx.x;
    if (rp >= g_cnt[0]) return;
    int bt  = g_idx[rp >> 2];
    int d   = rp & 3;
    int tid = threadIdx.x;

    const float* hrow = H    + (size_t)bt * DM;
    const float* erow = emb  + (size_t)ids[bt] * DM;
    const float* drow = demb + (size_t)d * DM;

    float x[4];
    float s = 0.f;
#pragma unroll
    for (int j = 0; j < 4; j++) {
        int i = j * 256 + tid;
        x[j] = hrow[i] + erow[i] + drow[i];
        s += x[j];
    }
    __shared__ float red[256];
    red[tid] = s; __syncthreads();
    for (int o = 128; o > 0; o >>= 1) { if (tid < o) red[tid] += red[tid + o]; __syncthreads(); }
    float mu = red[0] * (1.0f / DM);
    __syncthreads();

    float v = 0.f;
#pragma unroll
    for (int j = 0; j < 4; j++) { float dx = x[j] - mu; v += dx * dx; }
    red[tid] = v; __syncthreads();
    for (int o = 128; o > 0; o >>= 1) { if (tid < o) red[tid] += red[tid + o]; __syncthreads(); }
    float inv = rsqrtf(red[0] * (1.0f / DM) + 1e-5f);

#pragma unroll
    for (int j = 0; j < 4; j++) {
        int i = j * 256 + tid;
        float val = (x[j] - mu) * inv * lng[i] + lnb[i];
        __half h  = __float2half_rn(val);
        g_Shi[(size_t)rp * DM + i] = h;
        g_Slo[(size_t)rp * DM + i] = __float2half_rn(val - __half2float(h));
    }
}

// ---------------------------------------------------------------------------
#define KCH       32
#define ASTR2     20
#define BSTR2     136
#define A_TILE_H2 (128 * ASTR2)
#define B_TILE_H2 (16 * BSTR2)

// MODE 0: 2xFP16-split (3 HMMA), gelu -> g_G fp32 + g_Gh half.
// MODE 2: single pass, split-K, atomicAdd into bias-inited S2f.
// MODE 3: single pass (logits), scatter q + atomic exp-sum partials.
template<int MODE>
__global__ void __launch_bounds__(256, 2)
mlp_h_kernel(const __half* __restrict__ Ah, const __half* __restrict__ Al,
             const __half2* __restrict__ Bh, const __half2* __restrict__ Bl,
             const float* __restrict__ bias,
             float* __restrict__ O1, __half* __restrict__ Oh,
             int N, int K)
{
    constexpr int NARR  = (MODE == 0) ? 2 : 1;
    constexpr int STG   = NARR * (A_TILE_H2 + B_TILE_H2);

    const int nv4     = g_cnt[0];
    const int rowBase = blockIdx.x * 128;
    if (rowBase >= nv4) return;
    extern __shared__ uint32_t smh[];
    const uint32_t su = smem_u32(smh);
    const int tid     = threadIdx.x;
    const int colBase = blockIdx.y * 128;

    int koff  = 0;
    int niter = K / KCH;
    if (MODE == 2) {
        koff  = blockIdx.z * (K / SPLITK);
        niter = K / SPLITK / KCH;
    }

    const int lane = tid & 31, wid = tid >> 5;
    const int wr = wid >> 1, wc = wid & 1;
    const int g  = lane >> 2, tig = lane & 3;

    float acc[2][8][4];
#pragma unroll
    for (int mt = 0; mt < 2; mt++)
#pragma unroll
        for (int nt = 0; nt < 8; nt++)
#pragma unroll
            for (int k = 0; k < 4; k++) acc[mt][nt][k] = 0.f;

    const __half*  a0 = Ah + (size_t)rowBase * K + koff;
    const __half*  a1 = (NARR == 2) ? (Al + (size_t)rowBase * K + koff) : a0;
    const __half2* b0 = Bh + (size_t)(koff / 2) * N + colBase;
    const __half2* b1 = (NARR == 2) ? (Bl + (size_t)(koff / 2) * N + colBase) : b0;

    auto load_stage = [&](int s, int c) {
        const __half*  ap[2] = { a0, a1 };
        const __half2* bp[2] = { b0, b1 };
#pragma unroll
        for (int t = 0; t < NARR; t++) {
            uint32_t sa = su + (s * STG + t * A_TILE_H2) * 4;
            uint32_t sb = su + (s * STG + NARR * A_TILE_H2 + t * B_TILE_H2) * 4;
#pragma unroll
            for (int j = 0; j < 2; j++) {
                int idx = tid + 256 * j;
                int row = idx >> 2, seg = idx & 3;
                cp16(sa + (row * ASTR2 + seg * 4) * 4,
                     ap[t] + (size_t)row * K + c * KCH + seg * 8);
            }
#pragma unroll
            for (int j = 0; j < 2; j++) {
                int idx = tid + 256 * j;
                int k2r = idx >> 5, seg = idx & 31;
                cp16(sb + (k2r * BSTR2 + seg * 4) * 4,
                     bp[t] + (size_t)(c * 16 + k2r) * N + seg * 4);
            }
        }
    };

    load_stage(0, 0);
    CP_COMMIT();

    for (int it = 0; it < niter; it++) {
        int st = it & 1;
        CP_WAIT0();
        __syncthreads();
        if (it + 1 < niter) { load_stage(1 - st, it + 1); CP_COMMIT(); }

        const uint32_t* Ash = smh + st * STG;
        const uint32_t* Asl = Ash + A_TILE_H2;
        const uint32_t* Bsh = Ash + NARR * A_TILE_H2;
        const uint32_t* Bsl = Bsh + B_TILE_H2;

#pragma unroll
        for (int s = 0; s < 2; s++) {
            int s8 = s * 8;
            uint32_t ah[2][4], al[2][4];
#pragma unroll
            for (int mt = 0; mt < 2; mt++) {
                int m0 = wr * 32 + mt * 16;
                ah[mt][0] = Ash[(m0 + g    ) * ASTR2 + s8 + tig    ];
                ah[mt][1] = Ash[(m0 + g + 8) * ASTR2 + s8 + tig    ];
                ah[mt][2] = Ash[(m0 + g    ) * ASTR2 + s8 + tig + 4];
                ah[mt][3] = Ash[(m0 + g + 8) * ASTR2 + s8 + tig + 4];
                if (MODE == 0) {
                    al[mt][0] = Asl[(m0 + g    ) * ASTR2 + s8 + tig    ];
                    al[mt][1] = Asl[(m0 + g + 8) * ASTR2 + s8 + tig    ];
                    al[mt][2] = Asl[(m0 + g    ) * ASTR2 + s8 + tig + 4];
                    al[mt][3] = Asl[(m0 + g + 8) * ASTR2 + s8 + tig + 4];
                }
            }
            uint32_t bh[8][2], bl[8][2];
#pragma unroll
            for (int nt = 0; nt < 8; nt++) {
                int n0 = wc * 64 + nt * 8;
                bh[nt][0] = Bsh[(s8 + tig    ) * BSTR2 + n0 + g];
                bh[nt][1] = Bsh[(s8 + tig + 4) * BSTR2 + n0 + g];
                if (MODE == 0) {
                    bl[nt][0] = Bsl[(s8 + tig    ) * BSTR2 + n0 + g];
                    bl[nt][1] = Bsl[(s8 + tig + 4) * BSTR2 + n0 + g];
                }
            }
#pragma unroll
            for (int mt = 0; mt < 2; mt++)
#pragma unroll
                for (int nt = 0; nt < 8; nt++) {
                    mma_f16_16x8x16(acc[mt][nt], ah[mt], bh[nt]);
                    if (MODE == 0) {
                        mma_f16_16x8x16(acc[mt][nt], ah[mt], bl[nt]);
                        mma_f16_16x8x16(acc[mt][nt], al[mt], bh[nt]);
                    }
                }
        }
        __syncthreads();
    }

    // Epilogues
    if (MODE == 3) {
        float bqv[16];
#pragma unroll
        for (int nt = 0; nt < 8; nt++) {
            int c = colBase + wc * 64 + nt * 8 + tig * 2;
            bqv[nt * 2]     = bias[c];
            bqv[nt * 2 + 1] = bias[c + 1];
        }
#pragma unroll
        for (int mt = 0; mt < 2; mt++) {
            int rb  = rowBase + wr * 32 + mt * 16;
            int rc0 = rb + g, rc1 = rb + g + 8;
            bool ok0 = rc0 < nv4, ok1 = rc1 < nv4;
            int or0 = ok0 ? g_idx[rc0 >> 2] * 4 + (rc0 & 3) : 0;
            int or1 = ok1 ? g_idx[rc1 >> 2] * 4 + (rc1 & 3) : 0;
            float s0 = 0.f, s1 = 0.f;
#pragma unroll
            for (int nt = 0; nt < 8; nt++) {
                int c = colBase + wc * 64 + nt * 8 + tig * 2;
                float v00 = acc[mt][nt][0] + bqv[nt*2];
                float v01 = acc[mt][nt][1] + bqv[nt*2+1];
                float v10 = acc[mt][nt][2] + bqv[nt*2];
                float v11 = acc[mt][nt][3] + bqv[nt*2+1];
                s0 += __expf(v00) + __expf(v01);
                s1 += __expf(v10) + __expf(v11);
                if (ok0) *(float2*)&O1[(size_t)or0 * N + c] = make_float2(v00, v01);
                if (ok1) *(float2*)&O1[(size_t)or1 * N + c] = make_float2(v10, v11);
            }
            s0 += __shfl_xor_sync(0xffffffffu, s0, 1);
            s0 += __shfl_xor_sync(0xffffffffu, s0, 2);
            s1 += __shfl_xor_sync(0xffffffffu, s1, 1);
            s1 += __shfl_xor_sync(0xffffffffu, s1, 2);
            if (tig == 0) {
                if (ok0) atomicAdd(&g_sum[or0], s0);
                if (ok1) atomicAdd(&g_sum[or1], s1);
            }
        }
    } else {
#pragma unroll
        for (int mt = 0; mt < 2; mt++) {
            int rb  = rowBase + wr * 32 + mt * 16;
            int rc0 = rb + g, rc1 = rb + g + 8;
#pragma unroll
            for (int nt = 0; nt < 8; nt++) {
                int c = colBase + wc * 64 + nt * 8 + tig * 2;
                if (MODE == 2) {
                    atomicAdd(&O1[(size_t)rc0 * N + c    ], acc[mt][nt][0]);
                    atomicAdd(&O1[(size_t)rc0 * N + c + 1], acc[mt][nt][1]);
                    atomicAdd(&O1[(size_t)rc1 * N + c    ], acc[mt][nt][2]);
                    atomicAdd(&O1[(size_t)rc1 * N + c + 1], acc[mt][nt][3]);
                } else {  // MODE 0
                    float b0 = bias[c], b1v = bias[c + 1];
                    float v00 = acc[mt][nt][0] + b0, v01 = acc[mt][nt][1] + b1v;
                    float v10 = acc[mt][nt][2] + b0, v11 = acc[mt][nt][3] + b1v;
                    v00 = 0.5f * v00 * (1.0f + erff(v00 * 0.70710678118654752f));
                    v01 = 0.5f * v01 * (1.0f + erff(v01 * 0.70710678118654752f));
                    v10 = 0.5f * v10 * (1.0f + erff(v10 * 0.70710678118654752f));
                    v11 = 0.5f * v11 * (1.0f + erff(v11 * 0.70710678118654752f));
                    *(float2*)&O1[(size_t)rc0 * N + c] = make_float2(v00, v01);
                    *(float2*)&O1[(size_t)rc1 * N + c] = make_float2(v10, v11);
                    *(__half2*)&Oh[(size_t)rc0 * N + c] = __floats2half2_rn(v00, v01);
                    *(__half2*)&Oh[(size_t)rc1 * N + c] = __floats2half2_rn(v10, v11);
                }
            }
        }
    }
}

// ---------------------------------------------------------------------------
// Convert accumulated fp32 S2 to fp16 for the logits GEMM
__global__ void cvt_s2h_kernel()
{
    int i4 = blockIdx.x * 256 + threadIdx.x;
    if ((i4 >> 8) >= g_cnt[0]) return;
    size_t i = (size_t)i4 * 4;
    float4 v = *(const float4*)&g_S2f[i];
    __half2* dst = (__half2*)&g_S2h[i];
    dst[0] = __floats2half2_rn(v.x, v.y);
    dst[1] = __floats2half2_rn(v.z, v.w);
}

// ---------------------------------------------------------------------------
__global__ void beta_kernel(float* __restrict__ obeta, float* __restrict__ ok)
{
    int rp = blockIdx.x;
    if (rp >= g_cnt[0]) return;
    int tid = threadIdx.x;
    const float* row = g_G + (size_t)rp * DH;
    float s = 0.f;
    for (int i = tid; i < DH; i += 256) s += row[i] * g_w2b[i];
    __shared__ float red[256];
    red[tid] = s; __syncthreads();
    for (int o = 128; o > 0; o >>= 1) { if (tid < o) red[tid] += red[tid + o]; __syncthreads(); }
    if (tid == 0) {
        float be = red[0] + g_w2b[DH];
        int orow = g_idx[rp >> 2] * 4 + (rp & 3);
        obeta[orow]  = be;
        g_beta[orow] = be;
        float sig = 1.f / (1.f + expf(-be));
        int k = (int)ceilf(sig * 8.f);
        k = max(1, min(8, k));
        if (sig < 0.25f) k = 0;
        ok[orow] = (float)k;
    }
}

// ---------------------------------------------------------------------------
__global__ void nll_finish_kernel(const float* __restrict__ q,
                                  const int* __restrict__ mask,
                                  const int* __restrict__ labels)
{
    int r   = blockIdx.x * 256 + threadIdx.x;
    int tid = threadIdx.x;
    float nll = 0.f;
    int   cnt = 0;
    if (r < ROWS) {
        int d  = r & 3;
        int bt = r >> 2;
        int t  = bt % TT;
        int b  = bt / TT;
        int td = t + d + 1;
        if ((td < TT) && (mask[bt] != 0) && (mask[b * TT + td] != 0)) {
            int tgt = labels[b * TT + td];
            nll = logf(g_sum[r]) - q[(size_t)r * VV + tgt];
            cnt = 1;
        }
    }
    __shared__ float rn[256];
    __shared__ int   rc[256];
    rn[tid] = nll; rc[tid] = cnt; __syncthreads();
    for (int o = 128; o > 0; o >>= 1) {
        if (tid < o) { rn[tid] += rn[tid + o]; rc[tid] += rc[tid + o]; }
        __syncthreads();
    }
    if (tid == 0 && rc[0] > 0) {
        atomicAdd(&g_acc[0], (double)rn[0]);
        atomicAdd(&g_acc[1], (double)rc[0]);
    }
}

// ---------------------------------------------------------------------------
__global__ void bce_kernel(const int* __restrict__ mask)
{
    int idx = blockIdx.x * 256 + threadIdx.x;
    if (idx >= BTN) return;
    int t = idx % TT;
    int b = idx / TT;
    if (mask[idx] == 0) return;
    float bsum = 0.f;
    bool anyv = false;
#pragma unroll
    for (int d = 0; d < 4; d++) {
        int td = t + d + 1;
        bool valid = (td < TT) && (mask[b * TT + td] != 0);
        float be  = g_beta[idx * 4 + d];
        float bce = fmaxf(be, 0.f) + log1pf(expf(-fabsf(be))) - (valid ? be : 0.f);
        bsum += bce;
        anyv |= valid;
    }
    if (anyv) {
        atomicAdd(&g_acc[2], (double)bsum);
        atomicAdd(&g_acc[3], 1.0);
    }
}

// ---------------------------------------------------------------------------
__global__ void fin_kernel(float* __restrict__ oloss)
{
    double cnt = g_acc[1];
    double Lq  = (cnt > 0.0) ? g_acc[0] / cnt : 0.0;
    double den = g_acc[3]; if (den < 1.0) den = 1.0;
    double Lb  = g_acc[2] / den;
    oloss[0] = (float)(Lq + Lb);
}

// ---------------------------------------------------------------------------
extern "C" void kernel_launch(void* const* d_in, const int* in_sizes, int n_in,
                              void* d_out, int out_size)
{
    const float* H      = (const float*)d_in[0];
    const int*   ids    = (const int*)  d_in[1];
    const int*   mask   = (const int*)  d_in[2];
    const int*   labels = (const int*)  d_in[3];
    const float* emb    = (const float*)d_in[4];
    const float* demb   = (const float*)d_in[5];
    const float* ln_g   = (const float*)d_in[6];
    const float* ln_b   = (const float*)d_in[7];
    const float* W1     = (const float*)d_in[8];
    const float* b1     = (const float*)d_in[9];
    const float* W2     = (const float*)d_in[10];
    const float* b2     = (const float*)d_in[11];
    const float* Wq     = (const float*)d_in[12];
    const float* bq     = (const float*)d_in[13];
    const float* Wb     = (const float*)d_in[14];
    const float* bb     = (const float*)d_in[15];

    float* out   = (float*)d_out;
    float* q     = out;
    float* obeta = out + (size_t)ROWS * VV;
    float* ok    = obeta + ROWS;
    float* oloss = ok + ROWS;

    void *pShi, *pSlo, *pW1h, *pW1l, *pW2h, *pG, *pGh, *pS2f, *pS2h, *pWqh;
    cudaGetSymbolAddress(&pShi, g_Shi);
    cudaGetSymbolAddress(&pSlo, g_Slo);
    cudaGetSymbolAddress(&pW1h, g_W1h);
    cudaGetSymbolAddress(&pW1l, g_W1l);
    cudaGetSymbolAddress(&pW2h, g_W2h);
    cudaGetSymbolAddress(&pG,   g_G);
    cudaGetSymbolAddress(&pGh,  g_Gh);
    cudaGetSymbolAddress(&pS2f, g_S2f);
    cudaGetSymbolAddress(&pS2h, g_S2h);
    cudaGetSymbolAddress(&pWqh, g_Wqh);

    const int SM0 = 2 * 2 * (A_TILE_H2 + B_TILE_H2) * 4;
    const int SM1 = 2 * 1 * (A_TILE_H2 + B_TILE_H2) * 4;
    static bool init = false;
    static cudaStream_t s_prep, s_beta;
    static cudaEvent_t ev_fork, ev_w1, ev_w2b, ev_prep, ev_g, ev_beta;
    if (!init) {
        cudaFuncSetAttribute(mlp_h_kernel<0>,
                             cudaFuncAttributeMaxDynamicSharedMemorySize, SM0);
        cudaFuncSetAttribute(mlp_h_kernel<2>,
                             cudaFuncAttributeMaxDynamicSharedMemorySize, SM1);
        cudaFuncSetAttribute(mlp_h_kernel<3>,
                             cudaFuncAttributeMaxDynamicSharedMemorySize, SM1);
        cudaStreamCreateWithFlags(&s_prep, cudaStreamNonBlocking);
        cudaStreamCreateWithFlags(&s_beta, cudaStreamNonBlocking);
        cudaEventCreateWithFlags(&ev_fork, cudaEventDisableTiming);
        cudaEventCreateWithFlags(&ev_w1,   cudaEventDisableTiming);
        cudaEventCreateWithFlags(&ev_w2b,  cudaEventDisableTiming);
        cudaEventCreateWithFlags(&ev_prep, cudaEventDisableTiming);
        cudaEventCreateWithFlags(&ev_g,    cudaEventDisableTiming);
        cudaEventCreateWithFlags(&ev_beta, cudaEventDisableTiming);
        init = true;
    }

    // Fork: prep on s_prep; W1 pack FIRST (gates mlp0), then W2/w2b/s2init,
    // then the bulky Wq pack and zero_fill.
    cudaEventRecord(ev_fork, 0);
    cudaStreamWaitEvent(s_prep, ev_fork, 0);
    packw_kernel<<<dim3(DH / 256, DM / 2), 256, 0, s_prep>>>(
        W1, (__half2*)pW1h, (__half2*)pW1l, DH);
    cudaEventRecord(ev_w1, s_prep);
    packw_kernel<<<dim3(DM / 256, DH / 2), 256, 0, s_prep>>>(
        W2, (__half2*)pW2h, nullptr, DM);
    w2b_kernel<<<DH / 8 + 1, 256, 0, s_prep>>>(W2, Wb, b2, bb);
    s2init_kernel<<<ROWS * DM / 1024, 256, 0, s_prep>>>(b2);
    cudaEventRecord(ev_w2b, s_prep);
    packw_kernel<<<dim3(VV / 256, DM / 2), 256, 0, s_prep>>>(
        Wq, (__half2*)pWqh, nullptr, VV);
    zero_fill_kernel<<<BTN, 256, 0, s_prep>>>(mask, q, obeta, ok);
    cudaEventRecord(ev_prep, s_prep);

    // Main critical path
    compact_kernel<<<1, BTN>>>(mask);
    s_kernel<<<ROWS, 256>>>(H, ids, emb, demb, ln_g, ln_b);

    cudaStreamWaitEvent(0, ev_w1, 0);
    mlp_h_kernel<0><<<dim3(ROWS / 128, DH / 128), 256, SM0>>>(
        (const __half*)pShi, (const __half*)pSlo,
        (const __half2*)pW1h, (const __half2*)pW1l,
        b1, (float*)pG, (__half*)pGh, DH, DM);
    cudaEventRecord(ev_g, 0);

    // Side: beta + bce overlap with mlp2/cvt/logits
    cudaStreamWaitEvent(s_beta, ev_g, 0);
    cudaStreamWaitEvent(s_beta, ev_w2b, 0);
    beta_kernel<<<ROWS, 256, 0, s_beta>>>(obeta, ok);
    bce_kernel<<<(BTN + 255) / 256, 256, 0, s_beta>>>(mask);
    cudaEventRecord(ev_beta, s_beta);

    // Main: needs W2h + bias-inited S2f (covered by ev_w2b)
    cudaStreamWaitEvent(0, ev_w2b, 0);
    mlp_h_kernel<2><<<dim3(ROWS / 128, DM / 128, SPLITK), 256, SM1>>>(
        (const __half*)pGh, nullptr, (const __half2*)pW2h, nullptr,
        nullptr, (float*)pS2f, nullptr, DM, DH);

    cvt_s2h_kernel<<<ROWS * DM / 1024, 256>>>();

    // Logits needs Wqh (+ zero_fill ordering for output completeness)
    cudaStreamWaitEvent(0, ev_prep, 0);
    mlp_h_kernel<3><<<dim3(ROWS / 128, VV / 128), 256, SM1>>>(
        (const __half*)pS2h, nullptr, (const __half2*)pWqh, nullptr,
        bq, q, nullptr, VV, DM);

    nll_finish_kernel<<<ROWS / 256, 256>>>(q, mask, labels);

    cudaStreamWaitEvent(0, ev_beta, 0);
    fin_kernel<<<1, 1>>>(oloss);

    (void)in_sizes; (void)n_in; (void)out_size;
}

// round 15
// speedup vs baseline: 1.0063x; 1.0063x over previous
#include <cuda_runtime.h>
#include <cuda_fp16.h>
#include <math.h>
#include <stdint.h>

// Problem constants
#define BB   2
#define TT   512
#define DM   1024
#define DH   4096
#define DD   4
#define VV   32000
#define ROWS (BB*TT*DD)   // 4096
#define BTN  (BB*TT)      // 1024
#define SPLITK 4

// Scratch (static device globals — no allocation allowed)
__device__ __half  g_Shi[ROWS*DM];
__device__ __half  g_Slo[ROWS*DM];
__device__ __half2 g_W1h[(DM/2)*DH];
__device__ __half2 g_W1l[(DM/2)*DH];
__device__ __half2 g_W2h[(DH/2)*DM];
__device__ float   g_G  [ROWS*DH];         // fp32-exact gelu (beta path)
__device__ __half  g_Gh [ROWS*DH];         // fp16 gelu (q path)
__device__ float   g_P  [SPLITK*ROWS*DM];  // split-K partials for S2
__device__ __half  g_S2h[ROWS*DM];
__device__ __half2 g_Wqh[(DM/2)*VV];
__device__ float   g_w2b[DH+1];
__device__ float   g_beta[ROWS];
__device__ float   g_sum[ROWS];            // per-row sum(exp(q)); |q| small, no max needed
__device__ int     g_idx [BTN];
__device__ int     g_cnt [1];
__device__ double  g_acc[4];

// ============================================================================
__device__ __forceinline__ uint32_t smem_u32(const void* p) {
    uint32_t a;
    asm("{ .reg .u64 t; cvta.to.shared.u64 t, %1; cvt.u32.u64 %0, t; }"
        : "=r"(a) : "l"(p));
    return a;
}
__device__ __forceinline__ void cp16(uint32_t s, const void* g) {
    asm volatile("cp.async.cg.shared.global [%0], [%1], 16;" :: "r"(s), "l"(g));
}
#define CP_COMMIT() asm volatile("cp.async.commit_group;" ::: "memory")
#define CP_WAIT0()  asm volatile("cp.async.wait_group 0;" ::: "memory")

__device__ __forceinline__ void mma_f16_16x8x16(float* d, const uint32_t* a,
                                                const uint32_t* b) {
    asm volatile(
        "mma.sync.aligned.m16n8k16.row.col.f32.f16.f16.f32 "
        "{%0,%1,%2,%3}, {%4,%5,%6,%7}, {%8,%9}, {%0,%1,%2,%3};"
        : "+f"(d[0]), "+f"(d[1]), "+f"(d[2]), "+f"(d[3])
        : "r"(a[0]), "r"(a[1]), "r"(a[2]), "r"(a[3]), "r"(b[0]), "r"(b[1]));
}

// ============================================================================
// compact (warp-shuffle scan) + zero g_acc + zero g_sum
__global__ void compact_kernel(const int* __restrict__ mask) {
    __shared__ int wtot[32];
    int tid  = threadIdx.x;                // 1024
    int lane = tid & 31, warp = tid >> 5;
    if (tid < 4) g_acc[tid] = 0.0;
#pragma unroll
    for (int j = 0; j < 4; j++) g_sum[j * BTN + tid] = 0.f;

    int m = (mask[tid] != 0) ? 1 : 0;
    // intra-warp inclusive scan
    int p = m;
#pragma unroll
    for (int o = 1; o < 32; o <<= 1) {
        int v = __shfl_up_sync(0xffffffffu, p, o);
        if (lane >= o) p += v;
    }
    if (lane == 31) wtot[warp] = p;
    __syncthreads();
    if (warp == 0) {
        int w = wtot[lane];
#pragma unroll
        for (int o = 1; o < 32; o <<= 1) {
            int v = __shfl_up_sync(0xffffffffu, w, o);
            if (lane >= o) w += v;
        }
        wtot[lane] = w;                     // inclusive warp totals
    }
    __syncthreads();
    int pre = p + (warp > 0 ? wtot[warp - 1] : 0);   // inclusive prefix
    int mv  = wtot[31];
    if (m) g_idx[pre - 1] = tid;
    if (tid >= mv) g_idx[tid] = 0;
    if (tid == 0) g_cnt[0] = mv * 4;
}

// ---------------------------------------------------------------------------
__global__ void zero_fill_kernel(const int* __restrict__ mask,
                                 float* __restrict__ q,
                                 float* __restrict__ obeta,
                                 float* __restrict__ ok)
{
    int bt = blockIdx.x;
    if (mask[bt] != 0) return;
    int tid = threadIdx.x;
    float4* dst = (float4*)(q + (size_t)bt * 4 * VV);
#pragma unroll 4
    for (int i = tid; i < 32000; i += 256) dst[i] = make_float4(0.f, 0.f, 0.f, 0.f);
    if (tid < 4) {
        obeta[bt * 4 + tid] = 0.f;
        ok[bt * 4 + tid]    = 0.f;
    }
}

// ---------------------------------------------------------------------------
__global__ void w2b_kernel(const float* __restrict__ W2, const float* __restrict__ Wb,
                           const float* __restrict__ b2, const float* __restrict__ bb)
{
    if (blockIdx.x == DH / 8) {
        __shared__ float red[256];
        int tid = threadIdx.x;
        float s = 0.f;
        for (int i = tid; i < DM; i += 256) s += b2[i] * Wb[i];
        red[tid] = s; __syncthreads();
        for (int o = 128; o > 0; o >>= 1) { if (tid < o) red[tid] += red[tid + o]; __syncthreads(); }
        if (tid == 0) g_w2b[DH] = red[0] + bb[0];
        return;
    }
    int w = threadIdx.x >> 5, lane = threadIdx.x & 31;
    int j = blockIdx.x * 8 + w;
    const float* row = W2 + (size_t)j * DM;
    float s = 0.f;
    for (int i = lane; i < DM; i += 32) s += row[i] * Wb[i];
#pragma unroll
    for (int o = 16; o > 0; o >>= 1) s += __shfl_xor_sync(0xffffffffu, s, o);
    if (lane == 0) g_w2b[j] = s;
}

// ---------------------------------------------------------------------------
__global__ void packw_kernel(const float* __restrict__ W,
                             __half2* __restrict__ Dh, __half2* __restrict__ Dl,
                             int N)
{
    int n  = blockIdx.x * 256 + threadIdx.x;
    int k2 = blockIdx.y;
    float x0 = W[(size_t)(2 * k2    ) * N + n];
    float x1 = W[(size_t)(2 * k2 + 1) * N + n];
    __half h0 = __float2half_rn(x0), h1 = __float2half_rn(x1);
    Dh[(size_t)k2 * N + n] = __halves2half2(h0, h1);
    if (Dl)
        Dl[(size_t)k2 * N + n] = __halves2half2(
            __float2half_rn(x0 - __half2float(h0)),
            __float2half_rn(x1 - __half2float(h1)));
}

// ---------------------------------------------------------------------------
__global__ void s_kernel(const float* __restrict__ H, const int* __restrict__ ids,
                         const float* __restrict__ emb, const float* __restrict__ demb,
                         const float* __restrict__ lng, const float* __restrict__ lnb)
{
    int rp = blockIdx.x;
    if (rp >= g_cnt[0]) return;
    int bt  = g_idx[rp >> 2];
    int d   = rp & 3;
    int tid = threadIdx.x;

    const float* hrow = H    + (size_t)bt * DM;
    const float* erow = emb  + (size_t)ids[bt] * DM;
    const float* drow = demb + (size_t)d * DM;

    float x[4];
    float s = 0.f;
#pragma unroll
    for (int j = 0; j < 4; j++) {
        int i = j * 256 + tid;
        x[j] = hrow[i] + erow[i] + drow[i];
        s += x[j];
    }
    __shared__ float red[256];
    red[tid] = s; __syncthreads();
    for (int o = 128; o > 0; o >>= 1) { if (tid < o) red[tid] += red[tid + o]; __syncthreads(); }
    float mu = red[0] * (1.0f / DM);
    __syncthreads();

    float v = 0.f;
#pragma unroll
    for (int j = 0; j < 4; j++) { float dx = x[j] - mu; v += dx * dx; }
    red[tid] = v; __syncthreads();
    for (int o = 128; o > 0; o >>= 1) { if (tid < o) red[tid] += red[tid + o]; __syncthreads(); }
    float inv = rsqrtf(red[0] * (1.0f / DM) + 1e-5f);

#pragma unroll
    for (int j = 0; j < 4; j++) {
        int i = j * 256 + tid;
        float val = (x[j] - mu) * inv * lng[i] + lnb[i];
        __half h  = __float2half_rn(val);
        g_Shi[(size_t)rp * DM + i] = h;
        g_Slo[(size_t)rp * DM + i] = __float2half_rn(val - __half2float(h));
    }
}

// ---------------------------------------------------------------------------
#define KCH       32
#define ASTR2     20
#define BSTR2     136
#define A_TILE_H2 (128 * ASTR2)
#define B_TILE_H2 (16 * BSTR2)

// MODE 0: 2xFP16-split (3 HMMA), gelu -> g_G fp32 + g_Gh half.
// MODE 2: single pass, split-K raw partials -> g_P.
// MODE 3: single pass (logits), scatter q + atomic exp-sum partials.
template<int MODE>
__global__ void __launch_bounds__(256, 2)
mlp_h_kernel(const __half* __restrict__ Ah, const __half* __restrict__ Al,
             const __half2* __restrict__ Bh, const __half2* __restrict__ Bl,
             const float* __restrict__ bias,
             float* __restrict__ O1, __half* __restrict__ Oh,
             int N, int K)
{
    constexpr int NARR  = (MODE == 0) ? 2 : 1;
    constexpr int STG   = NARR * (A_TILE_H2 + B_TILE_H2);

    const int nv4     = g_cnt[0];
    const int rowBase = blockIdx.x * 128;
    if (rowBase >= nv4) return;
    extern __shared__ uint32_t smh[];
    const uint32_t su = smem_u32(smh);
    const int tid     = threadIdx.x;
    const int colBase = blockIdx.y * 128;

    int koff  = 0;
    int niter = K / KCH;
    if (MODE == 2) {
        koff  = blockIdx.z * (K / SPLITK);
        niter = K / SPLITK / KCH;
        O1   += (size_t)blockIdx.z * ROWS * DM;
    }

    const int lane = tid & 31, wid = tid >> 5;
    const int wr = wid >> 1, wc = wid & 1;
    const int g  = lane >> 2, tig = lane & 3;

    float acc[2][8][4];
#pragma unroll
    for (int mt = 0; mt < 2; mt++)
#pragma unroll
        for (int nt = 0; nt < 8; nt++)
#pragma unroll
            for (int k = 0; k < 4; k++) acc[mt][nt][k] = 0.f;

    const __half*  a0 = Ah + (size_t)rowBase * K + koff;
    const __half*  a1 = (NARR == 2) ? (Al + (size_t)rowBase * K + koff) : a0;
    const __half2* b0 = Bh + (size_t)(koff / 2) * N + colBase;
    const __half2* b1 = (NARR == 2) ? (Bl + (size_t)(koff / 2) * N + colBase) : b0;

    auto load_stage = [&](int s, int c) {
        const __half*  ap[2] = { a0, a1 };
        const __half2* bp[2] = { b0, b1 };
#pragma unroll
        for (int t = 0; t < NARR; t++) {
            uint32_t sa = su + (s * STG + t * A_TILE_H2) * 4;
            uint32_t sb = su + (s * STG + NARR * A_TILE_H2 + t * B_TILE_H2) * 4;
#pragma unroll
            for (int j = 0; j < 2; j++) {
                int idx = tid + 256 * j;
                int row = idx >> 2, seg = idx & 3;
                cp16(sa + (row * ASTR2 + seg * 4) * 4,
                     ap[t] + (size_t)row * K + c * KCH + seg * 8);
            }
#pragma unroll
            for (int j = 0; j < 2; j++) {
                int idx = tid + 256 * j;
                int k2r = idx >> 5, seg = idx & 31;
                cp16(sb + (k2r * BSTR2 + seg * 4) * 4,
                     bp[t] + (size_t)(c * 16 + k2r) * N + seg * 4);
            }
        }
    };

    load_stage(0, 0);
    CP_COMMIT();

    for (int it = 0; it < niter; it++) {
        int st = it & 1;
        CP_WAIT0();
        __syncthreads();
        if (it + 1 < niter) { load_stage(1 - st, it + 1); CP_COMMIT(); }

        const uint32_t* Ash = smh + st * STG;
        const uint32_t* Asl = Ash + A_TILE_H2;
        const uint32_t* Bsh = Ash + NARR * A_TILE_H2;
        const uint32_t* Bsl = Bsh + B_TILE_H2;

#pragma unroll
        for (int s = 0; s < 2; s++) {
            int s8 = s * 8;
            uint32_t ah[2][4], al[2][4];
#pragma unroll
            for (int mt = 0; mt < 2; mt++) {
                int m0 = wr * 32 + mt * 16;
                ah[mt][0] = Ash[(m0 + g    ) * ASTR2 + s8 + tig    ];
                ah[mt][1] = Ash[(m0 + g + 8) * ASTR2 + s8 + tig    ];
                ah[mt][2] = Ash[(m0 + g    ) * ASTR2 + s8 + tig + 4];
                ah[mt][3] = Ash[(m0 + g + 8) * ASTR2 + s8 + tig + 4];
                if (MODE == 0) {
                    al[mt][0] = Asl[(m0 + g    ) * ASTR2 + s8 + tig    ];
                    al[mt][1] = Asl[(m0 + g + 8) * ASTR2 + s8 + tig    ];
                    al[mt][2] = Asl[(m0 + g    ) * ASTR2 + s8 + tig + 4];
                    al[mt][3] = Asl[(m0 + g + 8) * ASTR2 + s8 + tig + 4];
                }
            }
            uint32_t bh[8][2], bl[8][2];
#pragma unroll
            for (int nt = 0; nt < 8; nt++) {
                int n0 = wc * 64 + nt * 8;
                bh[nt][0] = Bsh[(s8 + tig    ) * BSTR2 + n0 + g];
                bh[nt][1] = Bsh[(s8 + tig + 4) * BSTR2 + n0 + g];
                if (MODE == 0) {
                    bl[nt][0] = Bsl[(s8 + tig    ) * BSTR2 + n0 + g];
                    bl[nt][1] = Bsl[(s8 + tig + 4) * BSTR2 + n0 + g];
                }
            }
#pragma unroll
            for (int mt = 0; mt < 2; mt++)
#pragma unroll
                for (int nt = 0; nt < 8; nt++) {
                    mma_f16_16x8x16(acc[mt][nt], ah[mt], bh[nt]);
                    if (MODE == 0) {
                        mma_f16_16x8x16(acc[mt][nt], ah[mt], bl[nt]);
                        mma_f16_16x8x16(acc[mt][nt], al[mt], bh[nt]);
                    }
                }
        }
        __syncthreads();
    }

    // Epilogues
    if (MODE == 3) {
        float bqv[16];
#pragma unroll
        for (int nt = 0; nt < 8; nt++) {
            int c = colBase + wc * 64 + nt * 8 + tig * 2;
            bqv[nt * 2]     = bias[c];
            bqv[nt * 2 + 1] = bias[c + 1];
        }
#pragma unroll
        for (int mt = 0; mt < 2; mt++) {
            int rb  = rowBase + wr * 32 + mt * 16;
            int rc0 = rb + g, rc1 = rb + g + 8;
            bool ok0 = rc0 < nv4, ok1 = rc1 < nv4;
            int or0 = ok0 ? g_idx[rc0 >> 2] * 4 + (rc0 & 3) : 0;
            int or1 = ok1 ? g_idx[rc1 >> 2] * 4 + (rc1 & 3) : 0;
            float s0 = 0.f, s1 = 0.f;
#pragma unroll
            for (int nt = 0; nt < 8; nt++) {
                int c = colBase + wc * 64 + nt * 8 + tig * 2;
                float v00 = acc[mt][nt][0] + bqv[nt*2];
                float v01 = acc[mt][nt][1] + bqv[nt*2+1];
                float v10 = acc[mt][nt][2] + bqv[nt*2];
                float v11 = acc[mt][nt][3] + bqv[nt*2+1];
                s0 += __expf(v00) + __expf(v01);
                s1 += __expf(v10) + __expf(v11);
                if (ok0) *(float2*)&O1[(size_t)or0 * N + c] = make_float2(v00, v01);
                if (ok1) *(float2*)&O1[(size_t)or1 * N + c] = make_float2(v10, v11);
            }
            s0 += __shfl_xor_sync(0xffffffffu, s0, 1);
            s0 += __shfl_xor_sync(0xffffffffu, s0, 2);
            s1 += __shfl_xor_sync(0xffffffffu, s1, 1);
            s1 += __shfl_xor_sync(0xffffffffu, s1, 2);
            if (tig == 0) {
                if (ok0) atomicAdd(&g_sum[or0], s0);
                if (ok1) atomicAdd(&g_sum[or1], s1);
            }
        }
    } else {
#pragma unroll
        for (int mt = 0; mt < 2; mt++) {
            int rb  = rowBase + wr * 32 + mt * 16;
            int rc0 = rb + g, rc1 = rb + g + 8;
#pragma unroll
            for (int nt = 0; nt < 8; nt++) {
                int c = colBase + wc * 64 + nt * 8 + tig * 2;
                if (MODE == 2) {
                    *(float2*)&O1[(size_t)rc0 * N + c] =
                        make_float2(acc[mt][nt][0], acc[mt][nt][1]);
                    *(float2*)&O1[(size_t)rc1 * N + c] =
                        make_float2(acc[mt][nt][2], acc[mt][nt][3]);
                } else {  // MODE 0
                    float b0 = bias[c], b1v = bias[c + 1];
                    float v00 = acc[mt][nt][0] + b0, v01 = acc[mt][nt][1] + b1v;
                    float v10 = acc[mt][nt][2] + b0, v11 = acc[mt][nt][3] + b1v;
                    v00 = 0.5f * v00 * (1.0f + erff(v00 * 0.70710678118654752f));
                    v01 = 0.5f * v01 * (1.0f + erff(v01 * 0.70710678118654752f));
                    v10 = 0.5f * v10 * (1.0f + erff(v10 * 0.70710678118654752f));
                    v11 = 0.5f * v11 * (1.0f + erff(v11 * 0.70710678118654752f));
                    *(float2*)&O1[(size_t)rc0 * N + c] = make_float2(v00, v01);
                    *(float2*)&O1[(size_t)rc1 * N + c] = make_float2(v10, v11);
                    *(__half2*)&Oh[(size_t)rc0 * N + c] = __floats2half2_rn(v00, v01);
                    *(__half2*)&Oh[(size_t)rc1 * N + c] = __floats2half2_rn(v10, v11);
                }
            }
        }
    }
}

// ---------------------------------------------------------------------------
// Reduce split-K partials: S2h = half(sum + bias)
__global__ void reduce_s2h_kernel(const float* __restrict__ b2)
{
    int i4 = blockIdx.x * 256 + threadIdx.x;
    int row = i4 >> 8;
    if (row >= g_cnt[0]) return;
    size_t i = (size_t)i4 * 4;
    const float4 p0 = *(const float4*)&g_P[i];
    const float4 p1 = *(const float4*)&g_P[(size_t)ROWS * DM + i];
    const float4 p2 = *(const float4*)&g_P[2 * (size_t)ROWS * DM + i];
    const float4 p3 = *(const float4*)&g_P[3 * (size_t)ROWS * DM + i];
    int c = (i4 & 255) * 4;
    float4 bv = *(const float4*)&b2[c];
    float vx = ((p0.x + p1.x) + (p2.x + p3.x)) + bv.x;
    float vy = ((p0.y + p1.y) + (p2.y + p3.y)) + bv.y;
    float vz = ((p0.z + p1.z) + (p2.z + p3.z)) + bv.z;
    float vw = ((p0.w + p1.w) + (p2.w + p3.w)) + bv.w;
    __half2* dst = (__half2*)&g_S2h[i];
    dst[0] = __floats2half2_rn(vx, vy);
    dst[1] = __floats2half2_rn(vz, vw);
}

// ---------------------------------------------------------------------------
__global__ void beta_kernel(float* __restrict__ obeta, float* __restrict__ ok)
{
    int rp = blockIdx.x;
    if (rp >= g_cnt[0]) return;
    int tid = threadIdx.x;
    const float* row = g_G + (size_t)rp * DH;
    float s = 0.f;
    for (int i = tid; i < DH; i += 256) s += row[i] * g_w2b[i];
    __shared__ float red[256];
    red[tid] = s; __syncthreads();
    for (int o = 128; o > 0; o >>= 1) { if (tid < o) red[tid] += red[tid + o]; __syncthreads(); }
    if (tid == 0) {
        float be = red[0] + g_w2b[DH];
        int orow = g_idx[rp >> 2] * 4 + (rp & 3);
        obeta[orow]  = be;
        g_beta[orow] = be;
        float sig = 1.f / (1.f + expf(-be));
        int k = (int)ceilf(sig * 8.f);
        k = max(1, min(8, k));
        if (sig < 0.25f) k = 0;
        ok[orow] = (float)k;
    }
}

// ---------------------------------------------------------------------------
__global__ void nll_finish_kernel(const float* __restrict__ q,
                                  const int* __restrict__ mask,
                                  const int* __restrict__ labels)
{
    int r   = blockIdx.x * 256 + threadIdx.x;
    int tid = threadIdx.x;
    float nll = 0.f;
    int   cnt = 0;
    if (r < ROWS) {
        int d  = r & 3;
        int bt = r >> 2;
        int t  = bt % TT;
        int b  = bt / TT;
        int td = t + d + 1;
        if ((td < TT) && (mask[bt] != 0) && (mask[b * TT + td] != 0)) {
            int tgt = labels[b * TT + td];
            nll = logf(g_sum[r]) - q[(size_t)r * VV + tgt];
            cnt = 1;
        }
    }
    __shared__ float rn[256];
    __shared__ int   rc[256];
    rn[tid] = nll; rc[tid] = cnt; __syncthreads();
    for (int o = 128; o > 0; o >>= 1) {
        if (tid < o) { rn[tid] += rn[tid + o]; rc[tid] += rc[tid + o]; }
        __syncthreads();
    }
    if (tid == 0 && rc[0] > 0) {
        atomicAdd(&g_acc[0], (double)rn[0]);
        atomicAdd(&g_acc[1], (double)rc[0]);
    }
}

// ---------------------------------------------------------------------------
__global__ void bce_kernel(const int* __restrict__ mask)
{
    int idx = blockIdx.x * 256 + threadIdx.x;
    if (idx >= BTN) return;
    int t = idx % TT;
    int b = idx / TT;
    if (mask[idx] == 0) return;
    float bsum = 0.f;
    bool anyv = false;
#pragma unroll
    for (int d = 0; d < 4; d++) {
        int td = t + d + 1;
        bool valid = (td < TT) && (mask[b * TT + td] != 0);
        float be  = g_beta[idx * 4 + d];
        float bce = fmaxf(be, 0.f) + log1pf(expf(-fabsf(be))) - (valid ? be : 0.f);
        bsum += bce;
        anyv |= valid;
    }
    if (anyv) {
        atomicAdd(&g_acc[2], (double)bsum);
        atomicAdd(&g_acc[3], 1.0);
    }
}

// ---------------------------------------------------------------------------
__global__ void fin_kernel(float* __restrict__ oloss)
{
    double cnt = g_acc[1];
    double Lq  = (cnt > 0.0) ? g_acc[0] / cnt : 0.0;
    double den = g_acc[3]; if (den < 1.0) den = 1.0;
    double Lb  = g_acc[2] / den;
    oloss[0] = (float)(Lq + Lb);
}

// ---------------------------------------------------------------------------
extern "C" void kernel_launch(void* const* d_in, const int* in_sizes, int n_in,
                              void* d_out, int out_size)
{
    const float* H      = (const float*)d_in[0];
    const int*   ids    = (const int*)  d_in[1];
    const int*   mask   = (const int*)  d_in[2];
    const int*   labels = (const int*)  d_in[3];
    const float* emb    = (const float*)d_in[4];
    const float* demb   = (const float*)d_in[5];
    const float* ln_g   = (const float*)d_in[6];
    const float* ln_b   = (const float*)d_in[7];
    const float* W1     = (const float*)d_in[8];
    const float* b1     = (const float*)d_in[9];
    const float* W2     = (const float*)d_in[10];
    const float* b2     = (const float*)d_in[11];
    const float* Wq     = (const float*)d_in[12];
    const float* bq     = (const float*)d_in[13];
    const float* Wb     = (const float*)d_in[14];
    const float* bb     = (const float*)d_in[15];

    float* out   = (float*)d_out;
    float* q     = out;
    float* obeta = out + (size_t)ROWS * VV;
    float* ok    = obeta + ROWS;
    float* oloss = ok + ROWS;

    void *pShi, *pSlo, *pW1h, *pW1l, *pW2h, *pG, *pGh, *pP, *pS2h, *pWqh;
    cudaGetSymbolAddress(&pShi, g_Shi);
    cudaGetSymbolAddress(&pSlo, g_Slo);
    cudaGetSymbolAddress(&pW1h, g_W1h);
    cudaGetSymbolAddress(&pW1l, g_W1l);
    cudaGetSymbolAddress(&pW2h, g_W2h);
    cudaGetSymbolAddress(&pG,   g_G);
    cudaGetSymbolAddress(&pGh,  g_Gh);
    cudaGetSymbolAddress(&pP,   g_P);
    cudaGetSymbolAddress(&pS2h, g_S2h);
    cudaGetSymbolAddress(&pWqh, g_Wqh);

    const int SM0 = 2 * 2 * (A_TILE_H2 + B_TILE_H2) * 4;
    const int SM1 = 2 * 1 * (A_TILE_H2 + B_TILE_H2) * 4;
    static bool init = false;
    static cudaStream_t s_prep, s_beta;
    static cudaEvent_t ev_fork, ev_w1, ev_w2b, ev_prep, ev_g, ev_beta;
    if (!init) {
        cudaFuncSetAttribute(mlp_h_kernel<0>,
                             cudaFuncAttributeMaxDynamicSharedMemorySize, SM0);
        cudaFuncSetAttribute(mlp_h_kernel<2>,
                             cudaFuncAttributeMaxDynamicSharedMemorySize, SM1);
        cudaFuncSetAttribute(mlp_h_kernel<3>,
                             cudaFuncAttributeMaxDynamicSharedMemorySize, SM1);
        cudaStreamCreateWithFlags(&s_prep, cudaStreamNonBlocking);
        cudaStreamCreateWithFlags(&s_beta, cudaStreamNonBlocking);
        cudaEventCreateWithFlags(&ev_fork, cudaEventDisableTiming);
        cudaEventCreateWithFlags(&ev_w1,   cudaEventDisableTiming);
        cudaEventCreateWithFlags(&ev_w2b,  cudaEventDisableTiming);
        cudaEventCreateWithFlags(&ev_prep, cudaEventDisableTiming);
        cudaEventCreateWithFlags(&ev_g,    cudaEventDisableTiming);
        cudaEventCreateWithFlags(&ev_beta, cudaEventDisableTiming);
        init = true;
    }

    // Fork: prep on s_prep; W1 pack FIRST (gates mlp0), then W2/w2b, then the
    // bulky Wq pack and zero_fill.
    cudaEventRecord(ev_fork, 0);
    cudaStreamWaitEvent(s_prep, ev_fork, 0);
    packw_kernel<<<dim3(DH / 256, DM / 2), 256, 0, s_prep>>>(
        W1, (__half2*)pW1h, (__half2*)pW1l, DH);
    cudaEventRecord(ev_w1, s_prep);
    packw_kernel<<<dim3(DM / 256, DH / 2), 256, 0, s_prep>>>(
        W2, (__half2*)pW2h, nullptr, DM);
    w2b_kernel<<<DH / 8 + 1, 256, 0, s_prep>>>(W2, Wb, b2, bb);
    cudaEventRecord(ev_w2b, s_prep);
    packw_kernel<<<dim3(VV / 256, DM / 2), 256, 0, s_prep>>>(
        Wq, (__half2*)pWqh, nullptr, VV);
    zero_fill_kernel<<<BTN, 256, 0, s_prep>>>(mask, q, obeta, ok);
    cudaEventRecord(ev_prep, s_prep);

    // Main critical path
    compact_kernel<<<1, BTN>>>(mask);
    s_kernel<<<ROWS, 256>>>(H, ids, emb, demb, ln_g, ln_b);

    cudaStreamWaitEvent(0, ev_w1, 0);
    mlp_h_kernel<0><<<dim3(ROWS / 128, DH / 128), 256, SM0>>>(
        (const __half*)pShi, (const __half*)pSlo,
        (const __half2*)pW1h, (const __half2*)pW1l,
        b1, (float*)pG, (__half*)pGh, DH, DM);
    cudaEventRecord(ev_g, 0);

    // Side: beta + bce overlap with mlp2/reduce/logits
    cudaStreamWaitEvent(s_beta, ev_g, 0);
    cudaStreamWaitEvent(s_beta, ev_w2b, 0);
    beta_kernel<<<ROWS, 256, 0, s_beta>>>(obeta, ok);
    bce_kernel<<<(BTN + 255) / 256, 256, 0, s_beta>>>(mask);
    cudaEventRecord(ev_beta, s_beta);

    // Main: needs W2h (covered by ev_w2b)
    cudaStreamWaitEvent(0, ev_w2b, 0);
    mlp_h_kernel<2><<<dim3(ROWS / 128, DM / 128, SPLITK), 256, SM1>>>(
        (const __half*)pGh, nullptr, (const __half2*)pW2h, nullptr,
        nullptr, (float*)pP, nullptr, DM, DH);

    reduce_s2h_kernel<<<ROWS * DM / 1024, 256>>>(b2);

    // Logits needs Wqh (+ zero_fill ordering for output completeness)
    cudaStreamWaitEvent(0, ev_prep, 0);
    mlp_h_kernel<3><<<dim3(ROWS / 128, VV / 128), 256, SM1>>>(
        (const __half*)pS2h, nullptr, (const __half2*)pWqh, nullptr,
        bq, q, nullptr, VV, DM);

    nll_finish_kernel<<<ROWS / 256, 256>>>(q, mask, labels);

    cudaStreamWaitEvent(0, ev_beta, 0);
    fin_kernel<<<1, 1>>>(oloss);

    (void)in_sizes; (void)n_in; (void)out_size;
}